// round 15
// baseline (speedup 1.0000x reference)
#include <cuda_runtime.h>
#include <cuda_bf16.h>
#include <cstdint>

// Problem shape (fixed by the dataset): N=M=4096, DIM=8, TASKS=8
constexpr int NN   = 4096;
constexpr int MM   = 4096;
constexpr int DIMC = 8;
constexpr int TT   = 8;

constexpr int TR   = 32;    // rows per group (== warp size)
constexpr int TCW  = 256;   // columns per tile
constexpr int XT_S = 33;    // u-transposed stride
constexpr int XX_S = 9;     // padded xx stride (odd -> conflict-free compact reads)
constexpr int MAXG = 136;   // >= floor(4096/32) + (TASKS-1) = 135
constexpr int CNT_S = 129;  // sort count-array stride
constexpr int ZB   = 567;   // zero-fill CTAs in prep (total grid = 9 + ZB)

// Scratch (no cudaMalloc allowed)
__device__ int   g_perm[MAXG * TR];   // row indices grouped by task, -1 = pad
__device__ int   g_gtask[MAXG];       // task id per group, -1 = unused
__device__ float g_u[NN * DIMC];      // -2*inv2[t_r][d]*x[r][d]
__device__ float g_A2[NN];            // sum_d inv2*x^2 + log2(v[t_r])
__device__ float g_B[TT * MM];        // B[t][c] = sum_d inv2[t][d]*xx[c][d]^2

__device__ __forceinline__ float softplus_f(float a) {
    return (a > 20.0f) ? a : log1pf(__expf(a));
}

// ---------------------------------------------------------------------------
// Prep (9+ZB CTAs x 1024 thr):
//   CTAs 0-7  : rank-9 tables (g_u/g_A2/g_B)
//   CTA  8    : atomic-free counting sort (match_any + shfl warp-scan)
//   CTAs 9+   : grid-stride float4 zero-fill of out (64 MB)
// All three run concurrently; kernel duration ~= zero-fill (write-bound).
// ---------------------------------------------------------------------------
__global__ __launch_bounds__(1024) void rbf_prep(
    const int* __restrict__ i_task,
    const float* __restrict__ scale_raw,
    const float* __restrict__ var_raw,
    const float* __restrict__ x,
    const float* __restrict__ xx,
    float* __restrict__ out)
{
    const int tid = threadIdx.x;

    if (blockIdx.x >= 9) {
        // ================= zero-fill CTAs =================
        float4* o4 = (float4*)out;
        const int total = NN * MM / 4;                 // 4,194,304 float4
        const int stride = ZB * 1024;
        const float4 z = make_float4(0.f, 0.f, 0.f, 0.f);
        for (int i = (blockIdx.x - 9) * 1024 + tid; i < total; i += stride)
            o4[i] = z;
        return;
    }

    if (blockIdx.x < 8) {
        // ================= tables CTAs =================
        __shared__ float s_inv2[TT * DIMC];
        __shared__ float s_lv[TT];
        if (tid < TT * DIMC) {
            const int t = tid / DIMC, d = tid % DIMC;
            const float s = softplus_f(scale_raw[t * (TT * DIMC) + t * DIMC + d]);
            s_inv2[tid] = -0.5f * 1.4426950408889634f / (s * s);  // log2(e) folded
        }
        if (tid < TT) s_lv[tid] = log2f(softplus_f(var_raw[tid * TT + tid]));
        __syncthreads();

        if (tid < 512) {
            // rows: g_u, g_A2
            const int r = blockIdx.x * 512 + tid;
            const int t = i_task[r];
            const float4 a = *(const float4*)&x[r * DIMC + 0];
            const float4 b = *(const float4*)&x[r * DIMC + 4];
            float iv[DIMC];
#pragma unroll
            for (int d = 0; d < DIMC; d++) iv[d] = s_inv2[t * DIMC + d];
            float A = iv[0] * a.x * a.x;
            A = fmaf(iv[1], a.y * a.y, A); A = fmaf(iv[2], a.z * a.z, A);
            A = fmaf(iv[3], a.w * a.w, A); A = fmaf(iv[4], b.x * b.x, A);
            A = fmaf(iv[5], b.y * b.y, A); A = fmaf(iv[6], b.z * b.z, A);
            A = fmaf(iv[7], b.w * b.w, A);
            g_A2[r] = A + s_lv[t];
            *(float4*)&g_u[r * DIMC + 0] =
                make_float4(-2.f * iv[0] * a.x, -2.f * iv[1] * a.y,
                            -2.f * iv[2] * a.z, -2.f * iv[3] * a.w);
            *(float4*)&g_u[r * DIMC + 4] =
                make_float4(-2.f * iv[4] * b.x, -2.f * iv[5] * b.y,
                            -2.f * iv[6] * b.z, -2.f * iv[7] * b.w);
        } else {
            // cols: g_B for all 8 tasks
            const int c = blockIdx.x * 512 + (tid - 512);
            const float4 a = *(const float4*)&xx[c * DIMC + 0];
            const float4 b = *(const float4*)&xx[c * DIMC + 4];
            const float q0 = a.x * a.x, q1 = a.y * a.y, q2 = a.z * a.z, q3 = a.w * a.w;
            const float q4 = b.x * b.x, q5 = b.y * b.y, q6 = b.z * b.z, q7 = b.w * b.w;
#pragma unroll
            for (int t = 0; t < TT; t++) {
                float B = s_inv2[t * DIMC + 0] * q0;
                B = fmaf(s_inv2[t * DIMC + 1], q1, B);
                B = fmaf(s_inv2[t * DIMC + 2], q2, B);
                B = fmaf(s_inv2[t * DIMC + 3], q3, B);
                B = fmaf(s_inv2[t * DIMC + 4], q4, B);
                B = fmaf(s_inv2[t * DIMC + 5], q5, B);
                B = fmaf(s_inv2[t * DIMC + 6], q6, B);
                B = fmaf(s_inv2[t * DIMC + 7], q7, B);
                g_B[t * MM + c] = B;
            }
        }
        return;
    }

    // ================= sort CTA (blockIdx.x == 8) =================
    __shared__ int s_cnt[TT * CNT_S];
    __shared__ int s_excl[TT * CNT_S];
    __shared__ int s_wt[TT][4];
    __shared__ int s_tot[TT];
    __shared__ int base[TT];
    __shared__ int gbase[TT];
    __shared__ int ngr[TT];

    const int lane = tid & 31;
    const int wid  = tid >> 5;

    // zero counts (match_any stores only present tasks)
    if (tid < TT * CNT_S) s_cnt[tid] = 0;
    if (tid >= 1024 - 8) s_cnt[TT * CNT_S - (1024 - tid)] = 0;  // tail (1032>1024)
    __syncthreads();

    // ---- pass 1: per-chunk counts via match_any + own rank-in-chunk ----
    int myt[NN / 1024];
    int myrank[NN / 1024];
#pragma unroll
    for (int j = 0; j < NN / 1024; j++) {
        const int t = i_task[j * 1024 + tid];
        myt[j] = t;
        const int chunk = j * 32 + wid;
        const unsigned m_own = __match_any_sync(0xffffffffu, t);
        if (lane == (__ffs(m_own) - 1)) s_cnt[t * CNT_S + chunk] = __popc(m_own);
        myrank[j] = __popc(m_own & ((1u << lane) - 1u));
    }
    __syncthreads();

    // ---- pass 2: 128-wide scan per task via shfl warp-scan ----
    {
        const int u = tid >> 7;
        const int c = tid & 127;
        const int wir = c >> 5;
        const int orig = s_cnt[u * CNT_S + c];
        int v = orig;
#pragma unroll
        for (int off = 1; off < 32; off <<= 1) {
            const int tv = __shfl_up_sync(0xffffffffu, v, off);
            if (lane >= off) v += tv;
        }
        if (lane == 31) s_wt[u][wir] = v;
        __syncthreads();
        int add = 0;
#pragma unroll
        for (int j2 = 0; j2 < 3; j2++) if (wir > j2) add += s_wt[u][j2];
        s_excl[u * CNT_S + c] = v + add - orig;
        if (c == 127) s_tot[u] = v + add;
    }
    __syncthreads();

    // ---- pass 3: per-task bases + group table ----
    if (tid < TT) {
        int eb = 0, gb = 0;
        for (int u = 0; u < tid; u++) {
            const int g = (s_tot[u] + TR - 1) / TR;
            gb += g; eb += g * TR;
        }
        base[tid]  = eb;
        gbase[tid] = gb;
        ngr[tid]   = (s_tot[tid] + TR - 1) / TR;
    }
    __syncthreads();

    if (tid < MAXG) {
        int val = -1;
#pragma unroll
        for (int t = 0; t < TT; t++)
            if (tid >= gbase[t] && tid < gbase[t] + ngr[t]) val = t;
        g_gtask[tid] = val;
    }

    // pad-only init: at most 31 slots per task
    if (tid < TT * TR) {
        const int tt = tid >> 5, k = tid & 31;
        const int c = s_tot[tt];
        if (k < ngr[tt] * TR - c) g_perm[base[tt] + c + k] = -1;
    }

    // ---- pass 4: direct scatter, no atomics ----
#pragma unroll
    for (int j = 0; j < NN / 1024; j++) {
        const int r = j * 1024 + tid;
        const int t = myt[j];
        const int chunk = j * 32 + wid;
        g_perm[base[t] + s_excl[t * CNT_S + chunk] + myrank[j]] = r;
    }
}

// ---------------------------------------------------------------------------
// Main: one CTA = 32 rows (same task t) x 256 columns, 256 thr, 8 CTAs/SM.
// Output is pre-zeroed by rbf_prep, so this kernel writes ONLY matched cells,
// scattered STG.32 direct to gmem — no staging tile, no zero assembly.
//  phase A: match ballots (8 warps), xx re-packed into stride-9 smem
//           (conflict-free compact reads later), dense B, u/A row gather
//  phase B: compaction -> s_mcol, CNT
//  phase C: lanes = compact cols; warp w covers rows 4w..4w+3;
//           9 FFMA + FADD + EX2 + scattered STG.32 per cell
// 2 barriers total.
// ---------------------------------------------------------------------------
__global__ __launch_bounds__(256, 8) void rbf_main(
    const float* __restrict__ xx,
    const int*  __restrict__ ii,
    float* __restrict__ out)
{
    const int g = blockIdx.y;
    const int t = g_gtask[g];
    if (t < 0) return;

    const int c0   = blockIdx.x * TCW;
    const int tid  = threadIdx.x;
    const int lane = tid & 31;
    const int w    = tid >> 5;

    __shared__ int   s_mcol[TCW];              // compact idx -> col
    __shared__ int   s_wcnt[8];
    __shared__ int   s_rows[TR];
    __shared__ float s_A[TR];
    __shared__ float s_uT[DIMC * XT_S];        // u transposed [d][row]
    __shared__ float s_xx9[TCW * XX_S];        // xx padded stride 9 (9.2 KB)
    __shared__ float s_Bd[TCW];                // dense B tile

    // ---------------- phase A: ballots + all loads ----------------
    const int col = w * 32 + lane;             // each warp owns 32 cols
    const bool match = (ii[c0 + col] == t);
    const unsigned bal = __ballot_sync(0xffffffffu, match);
    if (lane == 0) s_wcnt[w] = __popc(bal);

    // xx tile re-packed to stride 9: thread tid owns col tid (coalesced LDG)
    {
        const float4 a = ((const float4*)(xx + (c0 + tid) * DIMC))[0];
        const float4 b = ((const float4*)(xx + (c0 + tid) * DIMC))[1];
        float* p = &s_xx9[tid * XX_S];
        p[0] = a.x; p[1] = a.y; p[2] = a.z; p[3] = a.w;
        p[4] = b.x; p[5] = b.y; p[6] = b.z; p[7] = b.w;
    }
    s_Bd[tid] = g_B[t * MM + c0 + tid];

    // u-row + A gather (8 threads per row, broadcast perm read)
    {
        const int r = tid >> 3;
        const int d = tid & 7;
        const int row = g_perm[g * TR + r];
        if (d == 0) {
            s_rows[r] = row;
            s_A[r] = (row >= 0) ? g_A2[row] : 0.0f;
        }
        s_uT[d * XT_S + r] = (row >= 0) ? g_u[row * DIMC + d] : 0.0f;
    }
    __syncthreads();

    // ---------------- phase B: compaction ----------------
    int basew = 0, CNT = 0;
#pragma unroll
    for (int u = 0; u < 8; u++) {
        const int cu = s_wcnt[u];
        if (u < w) basew += cu;
        CNT += cu;
    }
    if (match) s_mcol[basew + __popc(bal & ((1u << lane) - 1u))] = col;
    __syncthreads();

    // ---------------- phase C: compute + direct scatter ----------------
    for (int m0 = 0; m0 < CNT; m0 += 32) {
        const int m = m0 + lane;
        const bool mv = (m < CNT);
        const int cm = mv ? s_mcol[m] : 0;
        const float Bm = s_Bd[cm];
        const float* xp = &s_xx9[cm * XX_S];   // stride 9 -> conflict-free
        const float x0 = xp[0], x1 = xp[1], x2 = xp[2], x3 = xp[3];
        const float x4 = xp[4], x5 = xp[5], x6 = xp[6], x7 = xp[7];

#pragma unroll
        for (int r4 = 0; r4 < 4; r4++) {
            const int rg = w * 4 + r4;
            const int row = s_rows[rg];        // warp-uniform
            const float A = s_A[rg];           // LDS broadcast
            float sum = fmaf(s_uT[0 * XT_S + rg], x0, A);
            sum = fmaf(s_uT[1 * XT_S + rg], x1, sum);
            sum = fmaf(s_uT[2 * XT_S + rg], x2, sum);
            sum = fmaf(s_uT[3 * XT_S + rg], x3, sum);
            sum = fmaf(s_uT[4 * XT_S + rg], x4, sum);
            sum = fmaf(s_uT[5 * XT_S + rg], x5, sum);
            sum = fmaf(s_uT[6 * XT_S + rg], x6, sum);
            sum = fmaf(s_uT[7 * XT_S + rg], x7, sum);
            const float val = exp2f(sum + Bm);
            if (mv && row >= 0)
                out[(long)row * MM + c0 + cm] = val;   // scattered STG.32
        }
    }
}

// ---------------------------------------------------------------------------
extern "C" void kernel_launch(void* const* d_in, const int* in_sizes, int n_in,
                              void* d_out, int out_size)
{
    const float* x     = (const float*)d_in[0];
    const float* xx    = (const float*)d_in[1];
    const float* scale = (const float*)d_in[2];
    const float* var   = (const float*)d_in[3];
    const int*   i_t   = (const int*)d_in[4];
    const int*   ii_t  = (const int*)d_in[5];
    float* out = (float*)d_out;

    rbf_prep<<<9 + ZB, 1024>>>(i_t, scale, var, x, xx, out);

    dim3 grid(MM / TCW, MAXG);
    rbf_main<<<grid, 256>>>(xx, ii_t, out);
}

// round 16
// speedup vs baseline: 1.8119x; 1.8119x over previous
#include <cuda_runtime.h>
#include <cuda_bf16.h>
#include <cstdint>

// Problem shape (fixed by the dataset): N=M=4096, DIM=8, TASKS=8
constexpr int NN   = 4096;
constexpr int MM   = 4096;
constexpr int DIMC = 8;
constexpr int TT   = 8;

constexpr int TR   = 32;    // rows per group (== warp size)
constexpr int TCW  = 128;   // columns per tile
constexpr int TLS  = 132;   // staging-tile stride (16B-aligned rows, conflict-free LDS.128)
constexpr int XT_S = 33;    // u-transposed stride
constexpr int MAXG = 136;   // >= floor(4096/32) + (TASKS-1) = 135
constexpr int CNT_S = 129;  // sort count-array stride

// Scratch (no cudaMalloc allowed)
__device__ int   g_perm[MAXG * TR];   // row indices grouped by task, -1 = pad
__device__ int   g_gtask[MAXG];       // task id per group, -1 = unused
__device__ float g_u[NN * DIMC];      // -2*inv2[t_r][d]*x[r][d]
__device__ float g_A2[NN];            // sum_d inv2*x^2 + log2(v[t_r])
__device__ float g_B[TT * MM];        // B[t][c] = sum_d inv2[t][d]*xx[c][d]^2

__device__ __forceinline__ float softplus_f(float a) {
    return (a > 20.0f) ? a : log1pf(__expf(a));
}

// ---------------------------------------------------------------------------
// Prep (9 CTAs x 1024 thr): CTA 8 = atomic-free counting sort (match_any +
// shfl warp-scan); CTAs 0-7 = rank-9 tables (g_u/g_A2/g_B), fully parallel.
// (Unchanged from the 21.0us best; measured ~3.4us including launch overhead.)
// ---------------------------------------------------------------------------
__global__ __launch_bounds__(1024) void rbf_prep(
    const int* __restrict__ i_task,
    const float* __restrict__ scale_raw,
    const float* __restrict__ var_raw,
    const float* __restrict__ x,
    const float* __restrict__ xx)
{
    const int tid = threadIdx.x;

    if (blockIdx.x < 8) {
        // ================= tables CTAs =================
        __shared__ float s_inv2[TT * DIMC];
        __shared__ float s_lv[TT];
        if (tid < TT * DIMC) {
            const int t = tid / DIMC, d = tid % DIMC;
            const float s = softplus_f(scale_raw[t * (TT * DIMC) + t * DIMC + d]);
            s_inv2[tid] = -0.5f * 1.4426950408889634f / (s * s);  // log2(e) folded
        }
        if (tid < TT) s_lv[tid] = log2f(softplus_f(var_raw[tid * TT + tid]));
        __syncthreads();

        if (tid < 512) {
            // rows: g_u, g_A2
            const int r = blockIdx.x * 512 + tid;
            const int t = i_task[r];
            const float4 a = *(const float4*)&x[r * DIMC + 0];
            const float4 b = *(const float4*)&x[r * DIMC + 4];
            float iv[DIMC];
#pragma unroll
            for (int d = 0; d < DIMC; d++) iv[d] = s_inv2[t * DIMC + d];
            float A = iv[0] * a.x * a.x;
            A = fmaf(iv[1], a.y * a.y, A); A = fmaf(iv[2], a.z * a.z, A);
            A = fmaf(iv[3], a.w * a.w, A); A = fmaf(iv[4], b.x * b.x, A);
            A = fmaf(iv[5], b.y * b.y, A); A = fmaf(iv[6], b.z * b.z, A);
            A = fmaf(iv[7], b.w * b.w, A);
            g_A2[r] = A + s_lv[t];
            *(float4*)&g_u[r * DIMC + 0] =
                make_float4(-2.f * iv[0] * a.x, -2.f * iv[1] * a.y,
                            -2.f * iv[2] * a.z, -2.f * iv[3] * a.w);
            *(float4*)&g_u[r * DIMC + 4] =
                make_float4(-2.f * iv[4] * b.x, -2.f * iv[5] * b.y,
                            -2.f * iv[6] * b.z, -2.f * iv[7] * b.w);
        } else {
            // cols: g_B for all 8 tasks
            const int c = blockIdx.x * 512 + (tid - 512);
            const float4 a = *(const float4*)&xx[c * DIMC + 0];
            const float4 b = *(const float4*)&xx[c * DIMC + 4];
            const float q0 = a.x * a.x, q1 = a.y * a.y, q2 = a.z * a.z, q3 = a.w * a.w;
            const float q4 = b.x * b.x, q5 = b.y * b.y, q6 = b.z * b.z, q7 = b.w * b.w;
#pragma unroll
            for (int t = 0; t < TT; t++) {
                float B = s_inv2[t * DIMC + 0] * q0;
                B = fmaf(s_inv2[t * DIMC + 1], q1, B);
                B = fmaf(s_inv2[t * DIMC + 2], q2, B);
                B = fmaf(s_inv2[t * DIMC + 3], q3, B);
                B = fmaf(s_inv2[t * DIMC + 4], q4, B);
                B = fmaf(s_inv2[t * DIMC + 5], q5, B);
                B = fmaf(s_inv2[t * DIMC + 6], q6, B);
                B = fmaf(s_inv2[t * DIMC + 7], q7, B);
                g_B[t * MM + c] = B;
            }
        }
        return;
    }

    // ================= sort CTA =================
    __shared__ int s_cnt[TT * CNT_S];
    __shared__ int s_excl[TT * CNT_S];
    __shared__ int s_wt[TT][4];
    __shared__ int s_tot[TT];
    __shared__ int base[TT];
    __shared__ int gbase[TT];
    __shared__ int ngr[TT];

    const int lane = tid & 31;
    const int wid  = tid >> 5;

    // zero counts (match_any stores only present tasks)
    if (tid < TT * CNT_S) s_cnt[tid] = 0;
    if (tid >= 1024 - 8) s_cnt[TT * CNT_S - (1024 - tid)] = 0;  // tail (1032>1024)
    __syncthreads();

    // ---- pass 1: per-chunk counts via match_any + own rank-in-chunk ----
    int myt[NN / 1024];
    int myrank[NN / 1024];
#pragma unroll
    for (int j = 0; j < NN / 1024; j++) {
        const int t = i_task[j * 1024 + tid];
        myt[j] = t;
        const int chunk = j * 32 + wid;
        const unsigned m_own = __match_any_sync(0xffffffffu, t);
        if (lane == (__ffs(m_own) - 1)) s_cnt[t * CNT_S + chunk] = __popc(m_own);
        myrank[j] = __popc(m_own & ((1u << lane) - 1u));
    }
    __syncthreads();

    // ---- pass 2: 128-wide scan per task via shfl warp-scan ----
    {
        const int u = tid >> 7;
        const int c = tid & 127;
        const int wir = c >> 5;
        const int orig = s_cnt[u * CNT_S + c];
        int v = orig;
#pragma unroll
        for (int off = 1; off < 32; off <<= 1) {
            const int tv = __shfl_up_sync(0xffffffffu, v, off);
            if (lane >= off) v += tv;
        }
        if (lane == 31) s_wt[u][wir] = v;
        __syncthreads();
        int add = 0;
#pragma unroll
        for (int j2 = 0; j2 < 3; j2++) if (wir > j2) add += s_wt[u][j2];
        s_excl[u * CNT_S + c] = v + add - orig;
        if (c == 127) s_tot[u] = v + add;
    }
    __syncthreads();

    // ---- pass 3: per-task bases + group table ----
    if (tid < TT) {
        int eb = 0, gb = 0;
        for (int u = 0; u < tid; u++) {
            const int g = (s_tot[u] + TR - 1) / TR;
            gb += g; eb += g * TR;
        }
        base[tid]  = eb;
        gbase[tid] = gb;
        ngr[tid]   = (s_tot[tid] + TR - 1) / TR;
    }
    __syncthreads();

    if (tid < MAXG) {
        int val = -1;
#pragma unroll
        for (int t = 0; t < TT; t++)
            if (tid >= gbase[t] && tid < gbase[t] + ngr[t]) val = t;
        g_gtask[tid] = val;
    }

    // pad-only init: at most 31 slots per task
    if (tid < TT * TR) {
        const int tt = tid >> 5, k = tid & 31;
        const int c = s_tot[tt];
        if (k < ngr[tt] * TR - c) g_perm[base[tt] + c + k] = -1;
    }

    // ---- pass 4: direct scatter, no atomics ----
#pragma unroll
    for (int j = 0; j < NN / 1024; j++) {
        const int r = j * 1024 + tid;
        const int t = myt[j];
        const int chunk = j * 32 + wid;
        g_perm[base[t] + s_excl[t * CNT_S + chunk] + myrank[j]] = r;
    }
}

// ---------------------------------------------------------------------------
// Main: one CTA = 32 rows (same task t) x 128 columns, 256 thr, 8 CTAs/SM.
//  phase A: zero-fill the dense staging tile + all loads (match ballots,
//           dense s_xx/s_B, permuted u/A row gather) — all independent
//  phase B: compaction -> s_mcol (NO midx; tile is dense-addressed)
//  phase C: compute matched values, scatter STS.32 to tile[lane*132 + col]
//  phase D: plain LDS.128 -> STG.128 (no indirection, no predication)
// ---------------------------------------------------------------------------
__global__ __launch_bounds__(256, 8) void rbf_main(
    const float* __restrict__ xx,
    const int*  __restrict__ ii,
    float* __restrict__ out)
{
    const int g = blockIdx.y;
    const int t = g_gtask[g];
    if (t < 0) return;

    const int c0   = blockIdx.x * TCW;
    const int tid  = threadIdx.x;
    const int lane = tid & 31;
    const int w    = tid >> 5;

    __shared__ int   s_mcol[TCW];              // compact idx -> col
    __shared__ int   s_wcnt[4];
    __shared__ int   s_rows[TR];
    __shared__ float s_A[TR];
    __shared__ float s_uT[DIMC * XT_S];        // u transposed [d][row]
    __shared__ float s_xx[TCW * DIMC];         // dense xx tile (4 KB)
    __shared__ float s_B[TCW];                 // dense B tile
    __shared__ float s_tile[TR * TLS];         // dense staging tile (16.9 KB)

    // ---------------- phase A: zero-fill + all independent loads -----------
    unsigned bal = 0;
    bool match = false;
    if (w < 4) {
        const int col = w * 32 + lane;
        match = (ii[c0 + col] == t);
        bal = __ballot_sync(0xffffffffu, match);
        if (lane == 0) s_wcnt[w] = __popc(bal);
    }

    // zero-fill staging tile: 1056 float4 over 256 threads
    {
        const float4 z = make_float4(0.f, 0.f, 0.f, 0.f);
        float4* t4 = (float4*)s_tile;
#pragma unroll
        for (int i = tid; i < TR * TLS / 4; i += 256) t4[i] = z;
    }

    // dense xx tile: 1 float4 per thread, coalesced
    ((float4*)s_xx)[tid] = ((const float4*)(xx + c0 * DIMC))[tid];
    // dense B tile: threads 0-127, coalesced
    if (tid < TCW) s_B[tid] = g_B[t * MM + c0 + tid];

    // u-row + A gather (8 threads per row, broadcast perm read)
    {
        const int r = tid >> 3;
        const int d = tid & 7;
        const int row = g_perm[g * TR + r];
        if (d == 0) {
            s_rows[r] = row;
            s_A[r] = (row >= 0) ? g_A2[row] : 0.0f;
        }
        s_uT[d * XT_S + r] = (row >= 0) ? g_u[row * DIMC + d] : 0.0f;
    }
    __syncthreads();

    // ---------------- phase B: compaction (warps 0-3) ----------------
    const int b0 = s_wcnt[0], b1 = s_wcnt[1], b2 = s_wcnt[2], b3 = s_wcnt[3];
    const int CNT = b0 + b1 + b2 + b3;
    if (w < 4 && match) {
        const int col = w * 32 + lane;
        const int basew = (w >= 1 ? b0 : 0) + (w >= 2 ? b1 : 0) + (w >= 3 ? b2 : 0);
        s_mcol[basew + __popc(bal & ((1u << lane) - 1u))] = col;
    }
    __syncthreads();

    // ---------------- phase C: compute (lanes = rows) ----------------
    if (CNT > 0) {
        const float A = s_A[lane];
        const float u0 = s_uT[0 * XT_S + lane], u1 = s_uT[1 * XT_S + lane];
        const float u2 = s_uT[2 * XT_S + lane], u3 = s_uT[3 * XT_S + lane];
        const float u4 = s_uT[4 * XT_S + lane], u5 = s_uT[5 * XT_S + lane];
        const float u6 = s_uT[6 * XT_S + lane], u7 = s_uT[7 * XT_S + lane];

        int m = w;
        // unrolled-by-2 main loop (typical trip count is 2)
        for (; m + 8 < CNT; m += 16) {
            const int ca = s_mcol[m];
            const int cb = s_mcol[m + 8];
            const float4 xa0 = *(const float4*)&s_xx[ca * DIMC + 0];
            const float4 xb0 = *(const float4*)&s_xx[ca * DIMC + 4];
            const float4 xa1 = *(const float4*)&s_xx[cb * DIMC + 0];
            const float4 xb1 = *(const float4*)&s_xx[cb * DIMC + 4];
            float s0 = fmaf(u0, xa0.x, A);
            float s1 = fmaf(u0, xa1.x, A);
            s0 = fmaf(u1, xa0.y, s0);  s1 = fmaf(u1, xa1.y, s1);
            s0 = fmaf(u2, xa0.z, s0);  s1 = fmaf(u2, xa1.z, s1);
            s0 = fmaf(u3, xa0.w, s0);  s1 = fmaf(u3, xa1.w, s1);
            s0 = fmaf(u4, xb0.x, s0);  s1 = fmaf(u4, xb1.x, s1);
            s0 = fmaf(u5, xb0.y, s0);  s1 = fmaf(u5, xb1.y, s1);
            s0 = fmaf(u6, xb0.z, s0);  s1 = fmaf(u6, xb1.z, s1);
            s0 = fmaf(u7, xb0.w, s0);  s1 = fmaf(u7, xb1.w, s1);
            s_tile[lane * TLS + ca] = exp2f(s0 + s_B[ca]);
            s_tile[lane * TLS + cb] = exp2f(s1 + s_B[cb]);
        }
        if (m < CNT) {
            const int c = s_mcol[m];
            const float4 xa = *(const float4*)&s_xx[c * DIMC + 0];
            const float4 xb = *(const float4*)&s_xx[c * DIMC + 4];
            float sum = fmaf(u0, xa.x, A);
            sum = fmaf(u1, xa.y, sum);
            sum = fmaf(u2, xa.z, sum);
            sum = fmaf(u3, xa.w, sum);
            sum = fmaf(u4, xb.x, sum);
            sum = fmaf(u5, xb.y, sum);
            sum = fmaf(u6, xb.z, sum);
            sum = fmaf(u7, xb.w, sum);
            s_tile[lane * TLS + c] = exp2f(sum + s_B[c]);
        }
    }
    __syncthreads();

    // ---------------- phase D: plain tile flush ----------------
    // warp w -> rows 4w..4w+3; lane -> cols 4*lane..4*lane+3
#pragma unroll
    for (int rr = 0; rr < 4; rr++) {
        const int r = w * 4 + rr;
        const int row = s_rows[r];
        if (row >= 0) {
            const float4 v = *(const float4*)&s_tile[r * TLS + lane * 4];
            *(float4*)&out[(long)row * MM + c0 + lane * 4] = v;
        }
    }
}

// ---------------------------------------------------------------------------
extern "C" void kernel_launch(void* const* d_in, const int* in_sizes, int n_in,
                              void* d_out, int out_size)
{
    const float* x     = (const float*)d_in[0];
    const float* xx    = (const float*)d_in[1];
    const float* scale = (const float*)d_in[2];
    const float* var   = (const float*)d_in[3];
    const int*   i_t   = (const int*)d_in[4];
    const int*   ii_t  = (const int*)d_in[5];
    float* out = (float*)d_out;

    rbf_prep<<<9, 1024>>>(i_t, scale, var, x, xx);

    dim3 grid(MM / TCW, MAXG);
    rbf_main<<<grid, 256>>>(xx, ii_t, out);
}